// round 6
// baseline (speedup 1.0000x reference)
#include <cuda_runtime.h>
#include <math.h>

#define Bb 8
#define Cc 128
#define Nn 65536
#define Ll 64
#define PTS 512            // points per kmain block
#define SLC 128            // kmain blocks (slices) per batch
#define CHUNKS 8           // 64-point chunks per block

// Scratch in device globals. All fully overwritten every call.
__device__ float g_cpartC[Bb * SLC * Ll * Cc];   // 33.5 MB center partials
__device__ float g_vpart[Bb * SLC * Ll];
__device__ float g_cpart[Bb * SLC * Ll];
__device__ float g_cen[Bb * Ll * Cc];
__device__ float g_sqn[Bb * Cc];
__device__ float g_vc[Bb * Ll];

// ---------------------------------------------------------------------------
// kmain: fused single DRAM pass. Block = (b, slice of 512 pts), 256 threads.
// Per 64-pt chunk: all threads load swizzled tile [128c][64n]; then
//   warps 0-3 (t<128): scatter — thread owns channel t, RMW acc[lab][t]
//   warps 4-5 (t in [128,192)): per-point channel sums -> var terms
// Swizzle tile[c*64 + (n+c)&63] is conflict-free for all three patterns.
// ---------------------------------------------------------------------------
__global__ __launch_bounds__(256, 3) void kmain(const float* __restrict__ pred,
                                                const int* __restrict__ label,
                                                float* __restrict__ out, int out_size) {
    extern __shared__ float sm[];
    float* tile = sm;                   // [128*64]
    float* acc  = sm + 8192;            // [64 lab][128 ch]
    float* vbin = acc + 8192;           // [64]
    float* cbin = vbin + 64;            // [64]
    int*   slab = (int*)(cbin + 64);    // [64]

    const int t = threadIdx.x;
    const int bid = blockIdx.x;
    const int b = bid >> 7, s = bid & (SLC - 1);

    if (bid == 0)                       // zero output before kfin's atomics
        for (int i = t; i < out_size; i += 256) out[i] = 0.0f;

    for (int i = t; i < Ll * Cc; i += 256) acc[i] = 0.0f;
    if (t < Ll) { vbin[t] = 0.0f; cbin[t] = 0.0f; }

    const float* pb = pred + (size_t)b * Cc * Nn;
    const int n_base = s * PTS;
    __syncthreads();

#pragma unroll 1
    for (int ch = 0; ch < CHUNKS; ch++) {
        const int n0 = n_base + ch * 64;

        if (t >= 240)                   // 16 threads load 64 labels
            ((int4*)slab)[t - 240] = ((const int4*)(label + b * Nn + n0))[t - 240];

        // ---- load tile: 8 float4 per thread, coalesced gmem, swizzled smem
#pragma unroll
        for (int i = 0; i < 8; i++) {
            int idx = i * 256 + t;
            int c = idx >> 4, nq = (idx & 15) * 4;
            float4 v = *(const float4*)(pb + (size_t)c * Nn + n0 + nq);
            float* r = tile + c * 64;
            r[(nq + 0 + c) & 63] = v.x;
            r[(nq + 1 + c) & 63] = v.y;
            r[(nq + 2 + c) & 63] = v.z;
            r[(nq + 3 + c) & 63] = v.w;
        }
        __syncthreads();

        if (t < 128) {
            // ---- scatter: thread owns channel t; lanes same label -> addr
            // lab*128 + c consecutive -> conflict-free, no atomics
            float* ap = acc + t;
            const float* tr = tile + t * 64;
#pragma unroll 4
            for (int p = 0; p < 64; p++) {
                int lb = slab[p];
                ap[lb * Cc] += tr[(p + t) & 63];
            }
        } else if (t < 192) {
            // ---- per-point stats: thread owns point p, reads all 128 ch
            const int p = t - 128;
            float s1 = 0.f, s2 = 0.f;
#pragma unroll 16
            for (int j = 0; j < Cc; j++) {
                float x = tile[j * 64 + ((p + j) & 63)];
                s1 += x;
                s2 = fmaf(x, x, s2);
            }
            float pn2 = fmaxf(s2 - s1 * s1 * (1.0f / Cc), 0.f);
            float d = sqrtf(pn2) - 0.5f;             // D_VAR
            float v = (d > 0.f) ? d * d : 0.f;
            int lb = slab[p];
            atomicAdd(&vbin[lb], v);
            atomicAdd(&cbin[lb], 1.f);
        }
        __syncthreads();
    }

    // ---- writeback per-slice partials (plain coalesced stores)
    const size_t pbase = (size_t)bid * (Ll * Cc);
    for (int i = t; i < Ll * Cc; i += 256) g_cpartC[pbase + i] = acc[i];
    if (t < Ll) {
        g_vpart[bid * Ll + t] = vbin[t];
        g_cpart[bid * Ll + t] = cbin[t];
    }
}

// ---------------------------------------------------------------------------
// kred: reduce slice partials -> normalized centers, sqn, var terms.
// Grid (16, B): block g covers channels [g*8, g*8+8), all 64 labels.
// ---------------------------------------------------------------------------
__global__ __launch_bounds__(256) void kred() {
    const int g = blockIdx.x, b = blockIdx.y, t = threadIdx.x;
    __shared__ float ps[256];
    __shared__ float icnt[Ll];
    __shared__ float scen[Ll * 8];

    // counts (cooperative: 32 slices per thread)
    {
        const int l = t & 63, sg = t >> 6;
        float cs = 0.f;
#pragma unroll 8
        for (int k = 0; k < 32; k++)
            cs += g_cpart[(b * SLC + sg * 32 + k) * Ll + l];
        ps[t] = cs;
    }
    __syncthreads();
    if (t < Ll) icnt[t] = 1.0f / (ps[t] + ps[t + 64] + ps[t + 128] + ps[t + 192]);
    __syncthreads();

    // center cells: 2 per thread, slices interleaved for MLP
    {
        int cell0 = t, cell1 = t + 256;
        int l0 = cell0 >> 3, c0 = g * 8 + (cell0 & 7);
        int l1 = cell1 >> 3, c1 = g * 8 + (cell1 & 7);
        float a0 = 0.f, a1 = 0.f;
#pragma unroll 8
        for (int sl = 0; sl < SLC; sl++) {
            size_t base = (size_t)(b * SLC + sl) * (Ll * Cc);
            a0 += g_cpartC[base + l0 * Cc + c0];
            a1 += g_cpartC[base + l1 * Cc + c1];
        }
        float cv0 = a0 * icnt[l0], cv1 = a1 * icnt[l1];
        g_cen[(size_t)b * Ll * Cc + l0 * Cc + c0] = cv0;
        g_cen[(size_t)b * Ll * Cc + l1 * Cc + c1] = cv1;
        scen[l0 * 8 + (cell0 & 7)] = cv0;
        scen[l1 * 8 + (cell1 & 7)] = cv1;
    }

    // vsum (only g==0), overwrites ps after barrier
    __syncthreads();
    if (g == 0) {
        const int l = t & 63, sg = t >> 6;
        float vv = 0.f;
#pragma unroll 8
        for (int k = 0; k < 32; k++)
            vv += g_vpart[(b * SLC + sg * 32 + k) * Ll + l];
        ps[t] = vv;
    }
    __syncthreads();

    if (t < 8) {
        float q = 0.f;
#pragma unroll 8
        for (int l = 0; l < Ll; l++) { float v = scen[l * 8 + t]; q = fmaf(v, v, q); }
        g_sqn[b * Cc + g * 8 + t] = q;
    }
    if (g == 0 && t < Ll)
        g_vc[b * Ll + t] = (ps[t] + ps[t + 64] + ps[t + 128] + ps[t + 192]) * icnt[t];
}

// ---------------------------------------------------------------------------
// kfin: pairwise hinge + reg + var assembly. Grid (16, B): block q covers
// d in [q*8, q*8+8); two halves of the block give 4 accumulators each.
// ---------------------------------------------------------------------------
__global__ __launch_bounds__(256) void kfin(float* __restrict__ out) {
    const int q = blockIdx.x, b = blockIdx.y, t = threadIdx.x;
    __shared__ float cen[Ll][Cc];    // 32 KB
    __shared__ float sq[Cc];
    __shared__ float red[8];

    {   // vectorized centers load: 8 float4 per thread
        const float4* src = (const float4*)(g_cen + (size_t)b * Ll * Cc);
        float4* dst = (float4*)&cen[0][0];
#pragma unroll
        for (int i = 0; i < 8; i++) dst[i * 256 + t] = src[i * 256 + t];
    }
    if (t < Cc) sq[t] = g_sqn[b * Cc + t];
    __syncthreads();

    const int cc = t & 127;
    const int d0 = q * 8 + (t >> 7) * 4;
    float g0 = 0.f, g1 = 0.f, g2 = 0.f, g3 = 0.f;
#pragma unroll 8
    for (int l = 0; l < Ll; l++) {
        float a = cen[l][cc];
        g0 = fmaf(a, cen[l][d0 + 0], g0);
        g1 = fmaf(a, cen[l][d0 + 1], g1);
        g2 = fmaf(a, cen[l][d0 + 2], g2);
        g3 = fmaf(a, cen[l][d0 + 3], g3);
    }
    float gg[4] = {g0, g1, g2, g3};
    float local = 0.f;
#pragma unroll
    for (int j = 0; j < 4; j++) {
        float sqd = fmaxf(sq[cc] + sq[d0 + j] - 2.0f * gg[j], 0.f);
        float dist = (sqd > 0.f) ? sqrtf(sqd) : 0.f;
        float h = fmaxf(3.0f - dist, 0.f);        // 2*D_DIST
        local = fmaf(h, h, local);
    }
    local *= (1.0f / 8064.0f);                    // P_DIST / (2*L*(L-1))

    if (q == 0 && t < Cc) {
        local += 0.001f * sqrtf(sq[t]) * (1.0f / 64.0f);     // l_reg
        if (t < Ll) local += g_vc[b * Ll + t] * (1.0f / 64.0f); // var
    }

    for (int off = 16; off > 0; off >>= 1)
        local += __shfl_down_sync(0xFFFFFFFFu, local, off);
    if ((t & 31) == 0) red[t >> 5] = local;
    __syncthreads();
    if (t == 0) {
        float s = 0.f;
#pragma unroll
        for (int w = 0; w < 8; w++) s += red[w];
        atomicAdd(out, s);
    }
}

// ---------------------------------------------------------------------------
extern "C" void kernel_launch(void* const* d_in, const int* in_sizes, int n_in,
                              void* d_out, int out_size) {
    const float* pred  = (const float*)d_in[0];
    const int*   label = (const int*)d_in[1];
    float* out = (float*)d_out;

    const int smem_bytes = (8192 + 8192 + 64 + 64 + 64) * 4;   // 66304
    cudaFuncSetAttribute(kmain, cudaFuncAttributeMaxDynamicSharedMemorySize, smem_bytes);

    kmain<<<Bb * SLC, 256, smem_bytes>>>(pred, label, out, out_size);
    kred<<<dim3(16, Bb), 256>>>();
    kfin<<<dim3(16, Bb), 256>>>(out);
}